// round 2
// baseline (speedup 1.0000x reference)
#include <cuda_runtime.h>

// DETRsmpl iterative regression head, fused fp32.
// n = 115200 rows, C = 256, theta = 157 (padded 160).
// Restructured: xW1a precomputed once; W2@W3 folded to W23; iter-1 theta GEMM folded to c1.

#define TDIM 157
#define TPAD 160
#define TM 32
#define NTHREADS 256

// ---- device-global scratch (no allocation allowed) ----
__device__ float g_W1bp[TPAD * 256];   // W1 rows 256..412, zero-padded to 160 rows
__device__ float g_W23p[256 * TPAD];   // W2 @ W3, cols zero-padded to 160
__device__ float g_c1[256];            // theta0 @ W1b + b1
__device__ float g_b23[TPAD];          // b2 @ W3 + b3 (padded)
__device__ float g_theta0[TPAD];       // concat(init_contrep, init_shape, init_cam), padded

// ---------------- prep kernels (tiny) ----------------
__global__ void prep_theta0_k(const float* __restrict__ icr,
                              const float* __restrict__ ish,
                              const float* __restrict__ icam) {
    int t = threadIdx.x;  // 160
    float v = 0.f;
    if (t < 144)      v = icr[t];
    else if (t < 154) v = ish[t - 144];
    else if (t < 157) v = icam[t - 154];
    g_theta0[t] = v;
}

__global__ void prep_W1bp_k(const float* __restrict__ W1) {
    int t = blockIdx.x;   // 0..159
    int j = threadIdx.x;  // 0..255
    g_W1bp[t * 256 + j] = (t < 157) ? W1[(256 + t) * 256 + j] : 0.f;
}

__global__ void prep_c1_k(const float* __restrict__ W1, const float* __restrict__ b1) {
    int j = threadIdx.x;  // 0..255
    float s = b1[j];
    for (int t = 0; t < 157; t++)
        s = fmaf(g_theta0[t], W1[(256 + t) * 256 + j], s);
    g_c1[j] = s;
}

__global__ void prep_W23p_k(const float* __restrict__ W2, const float* __restrict__ W3) {
    int k = blockIdx.x;   // 0..255
    int j = threadIdx.x;  // 0..159
    float s = 0.f;
    if (j < 157) {
        for (int m = 0; m < 256; m++)
            s = fmaf(W2[k * 256 + m], W3[m * 157 + j], s);
    }
    g_W23p[k * TPAD + j] = s;
}

__global__ void prep_b23_k(const float* __restrict__ b2, const float* __restrict__ b3,
                           const float* __restrict__ W3) {
    int j = threadIdx.x;  // 0..159
    float s = 0.f;
    if (j < 157) {
        s = b3[j];
        for (int m = 0; m < 256; m++)
            s = fmaf(b2[m], W3[m * 157 + j], s);
    }
    g_b23[j] = s;
}

// ---------------- main fused kernel ----------------
// 16-wide fp32 dot-accumulate: p is 16B-aligned smem (broadcast across warp).
__device__ __forceinline__ float fma16(float acc, const float* __restrict__ p,
                                       const float* __restrict__ w) {
    const float4* q = reinterpret_cast<const float4*>(p);
    float4 a0 = q[0], a1 = q[1], a2 = q[2], a3 = q[3];
    acc = fmaf(a0.x, w[0], acc);  acc = fmaf(a0.y, w[1], acc);
    acc = fmaf(a0.z, w[2], acc);  acc = fmaf(a0.w, w[3], acc);
    acc = fmaf(a1.x, w[4], acc);  acc = fmaf(a1.y, w[5], acc);
    acc = fmaf(a1.z, w[6], acc);  acc = fmaf(a1.w, w[7], acc);
    acc = fmaf(a2.x, w[8], acc);  acc = fmaf(a2.y, w[9], acc);
    acc = fmaf(a2.z, w[10], acc); acc = fmaf(a2.w, w[11], acc);
    acc = fmaf(a3.x, w[12], acc); acc = fmaf(a3.y, w[13], acc);
    acc = fmaf(a3.z, w[14], acc); acc = fmaf(a3.w, w[15], acc);
    return acc;
}

__global__ __launch_bounds__(NTHREADS, 2)
void detr_main(const float* __restrict__ x, const float* __restrict__ W1,
               const float* __restrict__ b1, float* __restrict__ out, int nrows) {
    extern __shared__ float sm[];
    float* Ts = sm;                  // [TM][TPAD] theta tile
    float* Hs = Ts + TM * TPAD;      // [TM][256] relu activations
    float* xs = Hs + TM * 256;       // [TM][16] x k-block staging

    const int tid = threadIdx.x;
    const int row0 = blockIdx.x * TM;
    const float* xbase = x + (size_t)row0 * 256;

    // ---- Phase A: xw[r] = (x_tile @ W1a)[:, tid]  (iteration-invariant) ----
    float xw[TM];
#pragma unroll
    for (int r = 0; r < TM; r++) xw[r] = 0.f;

    for (int kb = 0; kb < 256; kb += 16) {
        __syncthreads();  // protect xs overwrite
        if (tid < TM * 4) {
            int r = tid >> 2, kq = tid & 3;
            *reinterpret_cast<float4*>(&xs[r * 16 + kq * 4]) =
                *reinterpret_cast<const float4*>(xbase + r * 256 + kb + kq * 4);
        }
        float w[16];
#pragma unroll
        for (int kk = 0; kk < 16; kk++)
            w[kk] = __ldg(&W1[(kb + kk) * 256 + tid]);
        __syncthreads();
#pragma unroll 8
        for (int r = 0; r < TM; r++)
            xw[r] = fma16(xw[r], &xs[r * 16], w);
    }

    // ---- 3 refinement iterations ----
    for (int it = 0; it < 3; ++it) {
        float u[TM];
        if (it == 0) {
            // theta is broadcast theta0 -> folded into c1
            float c = g_c1[tid];
#pragma unroll
            for (int r = 0; r < TM; r++) u[r] = xw[r] + c;
        } else {
#pragma unroll
            for (int r = 0; r < TM; r++) u[r] = 0.f;
            // tproj: theta_tile @ W1b  (K = 160 padded)
            for (int kb = 0; kb < TPAD; kb += 16) {
                float w[16];
#pragma unroll
                for (int kk = 0; kk < 16; kk++)
                    w[kk] = g_W1bp[(kb + kk) * 256 + tid];
#pragma unroll 8
                for (int r = 0; r < TM; r++)
                    u[r] = fma16(u[r], &Ts[r * TPAD + kb], w);
            }
            float c = b1[tid];
#pragma unroll
            for (int r = 0; r < TM; r++) u[r] += xw[r] + c;
        }
        // relu -> Hs
#pragma unroll
        for (int r = 0; r < TM; r++)
            Hs[r * 256 + tid] = fmaxf(u[r], 0.f);
        __syncthreads();

        // delta GEMM: h_tile(TMx256) @ W23(256x157->160), thread = output col
        if (tid < TPAD) {
            float acc[TM];
#pragma unroll
            for (int r = 0; r < TM; r++) acc[r] = 0.f;
            for (int kb = 0; kb < 256; kb += 16) {
                float w[16];
#pragma unroll
                for (int kk = 0; kk < 16; kk++)
                    w[kk] = g_W23p[(kb + kk) * TPAD + tid];
#pragma unroll 8
                for (int r = 0; r < TM; r++)
                    acc[r] = fma16(acc[r], &Hs[r * 256 + kb], w);
            }
            float bb = g_b23[tid];
            if (it == 0) {
                float t0 = g_theta0[tid];
#pragma unroll
                for (int r = 0; r < TM; r++)
                    Ts[r * TPAD + tid] = t0 + acc[r] + bb;
            } else {
#pragma unroll
                for (int r = 0; r < TM; r++)
                    Ts[r * TPAD + tid] += acc[r] + bb;
            }
        }
        __syncthreads();
    }

    // ---- epilogue: rot6d -> rotmat, betas, camera ----
    float* out_rot  = out;
    float* out_beta = out + (size_t)nrows * 216;
    float* out_cam  = out + (size_t)nrows * 226;

    for (int idx = tid; idx < TM * 24; idx += NTHREADS) {
        int r = idx / 24, g = idx - 24 * r;
        const float* tp = &Ts[r * TPAD + g * 6];
        // pose reshaped (3,2): column0=a1, column1=a2
        float a1x = tp[0], a2x = tp[1];
        float a1y = tp[2], a2y = tp[3];
        float a1z = tp[4], a2z = tp[5];
        float n1 = sqrtf(a1x * a1x + a1y * a1y + a1z * a1z);
        float i1 = 1.f / fmaxf(n1, 1e-12f);
        float b1x = a1x * i1, b1y = a1y * i1, b1z = a1z * i1;
        float d = b1x * a2x + b1y * a2y + b1z * a2z;
        float c2x = a2x - d * b1x, c2y = a2y - d * b1y, c2z = a2z - d * b1z;
        float n2 = sqrtf(c2x * c2x + c2y * c2y + c2z * c2z);
        float i2 = 1.f / fmaxf(n2, 1e-12f);
        float b2x = c2x * i2, b2y = c2y * i2, b2z = c2z * i2;
        float b3x = b1y * b2z - b1z * b2y;
        float b3y = b1z * b2x - b1x * b2z;
        float b3z = b1x * b2y - b1y * b2x;
        float* o = out_rot + (size_t)(row0 + r) * 216 + g * 9;
        o[0] = b1x; o[1] = b2x; o[2] = b3x;
        o[3] = b1y; o[4] = b2y; o[5] = b3y;
        o[6] = b1z; o[7] = b2z; o[8] = b3z;
    }
    for (int idx = tid; idx < TM * 13; idx += NTHREADS) {
        int r = idx / 13, c = idx - 13 * r;
        if (c < 10)
            out_beta[(size_t)(row0 + r) * 10 + c] = Ts[r * TPAD + 144 + c];
        else
            out_cam[(size_t)(row0 + r) * 3 + (c - 10)] = Ts[r * TPAD + 154 + (c - 10)];
    }
}

// ---------------- launch ----------------
extern "C" void kernel_launch(void* const* d_in, const int* in_sizes, int n_in,
                              void* d_out, int out_size) {
    const float* x    = (const float*)d_in[0];
    // d_in[1] = pred_class (unused by reference)
    const float* W1   = (const float*)d_in[2];
    const float* b1   = (const float*)d_in[3];
    const float* W2   = (const float*)d_in[4];
    const float* b2   = (const float*)d_in[5];
    const float* W3   = (const float*)d_in[6];
    const float* b3   = (const float*)d_in[7];
    const float* icr  = (const float*)d_in[8];
    const float* ish  = (const float*)d_in[9];
    const float* icam = (const float*)d_in[10];
    float* out = (float*)d_out;

    int nrows = in_sizes[0] / 256;  // 115200

    prep_theta0_k<<<1, TPAD>>>(icr, ish, icam);
    prep_W1bp_k<<<TPAD, 256>>>(W1);
    prep_c1_k<<<1, 256>>>(W1, b1);
    prep_W23p_k<<<256, TPAD>>>(W2, W3);
    prep_b23_k<<<1, TPAD>>>(b2, b3, W3);

    int smem = (TM * TPAD + TM * 256 + TM * 16) * (int)sizeof(float);  // 55296 B
    cudaFuncSetAttribute(detr_main, cudaFuncAttributeMaxDynamicSharedMemorySize, smem);
    detr_main<<<nrows / TM, NTHREADS, smem>>>(x, W1, b1, out, nrows);
}

// round 4
// speedup vs baseline: 1.3756x; 1.3756x over previous
#include <cuda_runtime.h>
#include <cuda_bf16.h>
#include <mma.h>
#include <cstdint>

using namespace nvcuda;

// ============================================================================
// DETRsmpl head via classic HMMA (wmma bf16, 3-term hi/lo split, fp32 accum).
// Base sm_103 target: no tcgen05 available (harness PTX target lacks 'a').
// n=115200 rows, C=256, theta=157(pad 160), 3 iters. 64 rows/CTA, 1800 CTAs.
// Folded: W23 = W2@W3 ; c1 = theta0@W1b + b1 ; b23 = b2@W3 + b3.
// u-GEMM: [x|theta] @ W1 (K=256 iter0 via c1-fold, else 416 eff), N=256.
// delta-GEMM: h @ W23, K=256, N=160.
// ============================================================================

#define NT 512
#define MR 64
#define THS 161      // theta row stride (f32)
#define ALD 40       // A-chunk ld (32 + 8 pad, bf16)
#define HLD 264      // H ld (256 + 8 pad, bf16)

// smem byte offsets
#define OFF_TH   0        // th  f32 [64][161]          = 41216
#define OFF_AH   41216    // Ah  bf16 [64][40]          = 5120
#define OFF_AL   46336    // Al  bf16 [64][40]          = 5120
#define OFF_HH   51456    // Hh  bf16 [64][264]         = 33792
#define OFF_HL   85248    // Hl  bf16 [64][264]         = 33792
#define OFF_SCR  119040   // scratch f32 16 warps x 256 = 16384
#define OFF_SB   135424   // bias f32 [256]             = 1024
#define SMEM_SZ  136448

// ---- device-global weight images (pre-split bf16 hi/lo) ----
__device__ __nv_bfloat16 g_W1h[448 * 256];   // [k][n], rows >=413 zero
__device__ __nv_bfloat16 g_W1l[448 * 256];
__device__ __nv_bfloat16 g_W23h[256 * 160];  // [k][n], cols >=157 zero
__device__ __nv_bfloat16 g_W23l[256 * 160];
__device__ float g_W23p[256 * 160];
__device__ float g_c1[256];
__device__ float g_b23[160];
__device__ float g_theta0[160];

// ---------------- helpers ----------------
__device__ __forceinline__ uint32_t pk2(__nv_bfloat16 a, __nv_bfloat16 b) {
    return (uint32_t)__bfloat16_as_ushort(a) | ((uint32_t)__bfloat16_as_ushort(b) << 16);
}

__device__ __forceinline__ void splitstore4(__nv_bfloat16* ph, __nv_bfloat16* pl, float4 v) {
    __nv_bfloat16 h0 = __float2bfloat16(v.x), h1 = __float2bfloat16(v.y);
    __nv_bfloat16 h2 = __float2bfloat16(v.z), h3 = __float2bfloat16(v.w);
    __nv_bfloat16 l0 = __float2bfloat16(v.x - __bfloat162float(h0));
    __nv_bfloat16 l1 = __float2bfloat16(v.y - __bfloat162float(h1));
    __nv_bfloat16 l2 = __float2bfloat16(v.z - __bfloat162float(h2));
    __nv_bfloat16 l3 = __float2bfloat16(v.w - __bfloat162float(h3));
    *reinterpret_cast<uint2*>(ph) = make_uint2(pk2(h0, h1), pk2(h2, h3));
    *reinterpret_cast<uint2*>(pl) = make_uint2(pk2(l0, l1), pk2(l2, l3));
}

// ---------------- prep kernels ----------------
__global__ void prep_theta0_k(const float* __restrict__ icr, const float* __restrict__ ish,
                              const float* __restrict__ icam) {
    int t = threadIdx.x;  // 160
    float v = 0.f;
    if (t < 144) v = icr[t];
    else if (t < 154) v = ish[t - 144];
    else if (t < 157) v = icam[t - 154];
    g_theta0[t] = v;
}

__global__ void prep_W23p_k(const float* __restrict__ W2, const float* __restrict__ W3) {
    int k = blockIdx.x, j = threadIdx.x;  // 256 x 160
    float s0 = 0, s1 = 0, s2 = 0, s3 = 0;
    if (j < 157) {
        for (int m = 0; m < 256; m += 4) {
            s0 = fmaf(W2[k * 256 + m + 0], W3[(m + 0) * 157 + j], s0);
            s1 = fmaf(W2[k * 256 + m + 1], W3[(m + 1) * 157 + j], s1);
            s2 = fmaf(W2[k * 256 + m + 2], W3[(m + 2) * 157 + j], s2);
            s3 = fmaf(W2[k * 256 + m + 3], W3[(m + 3) * 157 + j], s3);
        }
    }
    g_W23p[k * 160 + j] = (s0 + s1) + (s2 + s3);
}

__global__ void prep_c1_k(const float* __restrict__ W1, const float* __restrict__ b1) {
    int j = threadIdx.x;  // 256
    float s = b1[j];
    for (int t = 0; t < 157; t++)
        s = fmaf(g_theta0[t], W1[(256 + t) * 256 + j], s);
    g_c1[j] = s;
}

__global__ void prep_b23_k(const float* __restrict__ b2, const float* __restrict__ b3,
                           const float* __restrict__ W3) {
    int j = threadIdx.x;  // 160
    float s = 0.f;
    if (j < 157) {
        s = b3[j];
        for (int m = 0; m < 256; m++)
            s = fmaf(b2[m], W3[m * 157 + j], s);
    }
    g_b23[j] = s;
}

__global__ void prep_splitW1_k(const float* __restrict__ W1) {
    int k = blockIdx.x;   // 0..447
    int n = threadIdx.x;  // 0..255
    float v = (k < 413) ? W1[k * 256 + n] : 0.f;
    __nv_bfloat16 h = __float2bfloat16(v);
    __nv_bfloat16 l = __float2bfloat16(v - __bfloat162float(h));
    g_W1h[k * 256 + n] = h;
    g_W1l[k * 256 + n] = l;
}

__global__ void prep_splitW23_k() {
    int k = blockIdx.x;   // 0..255
    int n = threadIdx.x;  // 0..159
    float v = g_W23p[k * 160 + n];
    __nv_bfloat16 h = __float2bfloat16(v);
    __nv_bfloat16 l = __float2bfloat16(v - __bfloat162float(h));
    g_W23h[k * 160 + n] = h;
    g_W23l[k * 160 + n] = l;
}

// ---------------- main kernel ----------------
typedef wmma::fragment<wmma::matrix_a, 16, 16, 16, __nv_bfloat16, wmma::row_major> FragA;
typedef wmma::fragment<wmma::matrix_b, 16, 16, 16, __nv_bfloat16, wmma::row_major> FragB;
typedef wmma::fragment<wmma::accumulator, 16, 16, 16, float> FragC;

__global__ __launch_bounds__(NT, 1)
void detr_wmma(const float* __restrict__ x, const float* __restrict__ b1g,
               float* __restrict__ out, int nrows) {
    extern __shared__ char smc[];
    float* th = reinterpret_cast<float*>(smc + OFF_TH);
    __nv_bfloat16* Ah = reinterpret_cast<__nv_bfloat16*>(smc + OFF_AH);
    __nv_bfloat16* Al = reinterpret_cast<__nv_bfloat16*>(smc + OFF_AL);
    __nv_bfloat16* Hh = reinterpret_cast<__nv_bfloat16*>(smc + OFF_HH);
    __nv_bfloat16* Hl = reinterpret_cast<__nv_bfloat16*>(smc + OFF_HL);
    float* scr = reinterpret_cast<float*>(smc + OFF_SCR);
    float* sbias = reinterpret_cast<float*>(smc + OFF_SB);

    const int tid = threadIdx.x;
    const int w = tid >> 5, lane = tid & 31;
    const int row0 = blockIdx.x * MR;
    float* wscr = scr + w * 256;

    // init theta tile = broadcast theta0
    for (int i = tid; i < MR * 160; i += NT) {
        int r = i / 160, c = i - 160 * r;
        th[r * THS + c] = g_theta0[c];
    }
    __syncthreads();

    for (int it = 0; it < 3; it++) {
        // stage bias (c1 folds theta0@W1b+b1 for iter 0)
        if (tid < 256) sbias[tid] = (it == 0) ? g_c1[tid] : b1g[tid];

        // ========== u-GEMM: [x | theta] @ W1  -> acc (N=256, warp w owns 16 cols)
        FragC acc[4];
#pragma unroll
        for (int m = 0; m < 4; m++) wmma::fill_fragment(acc[m], 0.f);

        const int NC = (it == 0) ? 8 : 13;  // 8 x-chunks (+5 theta-chunks)
        for (int kc = 0; kc < NC; kc++) {
            __syncthreads();  // protect A reuse
            {   // stage A chunk: 64 rows x 32 k, one float4 per thread
                int r = tid >> 3, c4 = tid & 7;
                float4 v;
                if (kc < 8) {
                    v = *reinterpret_cast<const float4*>(
                        x + (size_t)(row0 + r) * 256 + kc * 32 + c4 * 4);
                } else {
                    const float* tr = &th[r * THS + (kc - 8) * 32 + c4 * 4];
                    v = make_float4(tr[0], tr[1], tr[2], tr[3]);
                }
                splitstore4(&Ah[r * ALD + c4 * 4], &Al[r * ALD + c4 * 4], v);
            }
            __syncthreads();

            FragA fah, fal;
            FragB fbh, fbl;
#pragma unroll
            for (int ks = 0; ks < 2; ks++) {
                const int kg = kc * 32 + ks * 16;
                wmma::load_matrix_sync(fbh, g_W1h + kg * 256 + w * 16, 256);
                wmma::load_matrix_sync(fbl, g_W1l + kg * 256 + w * 16, 256);
#pragma unroll
                for (int m = 0; m < 4; m++) {
                    wmma::load_matrix_sync(fah, Ah + m * 16 * ALD + ks * 16, ALD);
                    wmma::load_matrix_sync(fal, Al + m * 16 * ALD + ks * 16, ALD);
                    wmma::mma_sync(acc[m], fah, fbh, acc[m]);
                    wmma::mma_sync(acc[m], fah, fbl, acc[m]);
                    wmma::mma_sync(acc[m], fal, fbh, acc[m]);
                }
            }
        }

        // ========== bias + relu + split -> H panels
#pragma unroll
        for (int m = 0; m < 4; m++) {
            wmma::store_matrix_sync(wscr, acc[m], 16, wmma::mem_row_major);
            __syncwarp();
#pragma unroll
            for (int e = 0; e < 8; e++) {
                int idx = lane * 8 + e;
                int r = idx >> 4, c = idx & 15;
                float v = fmaxf(wscr[r * 16 + c] + sbias[w * 16 + c], 0.f);
                __nv_bfloat16 h = __float2bfloat16(v);
                __nv_bfloat16 l = __float2bfloat16(v - __bfloat162float(h));
                Hh[(m * 16 + r) * HLD + w * 16 + c] = h;
                Hl[(m * 16 + r) * HLD + w * 16 + c] = l;
            }
            __syncwarp();
        }
        __syncthreads();

        // ========== delta-GEMM: h @ W23 (K=256, N=160 -> 10 warps)
        if (w < 10) {
            FragC dacc[4];
#pragma unroll
            for (int m = 0; m < 4; m++) wmma::fill_fragment(dacc[m], 0.f);
            FragA fah, fal;
            FragB fbh, fbl;
#pragma unroll 2
            for (int ks = 0; ks < 16; ks++) {
                wmma::load_matrix_sync(fbh, g_W23h + ks * 16 * 160 + w * 16, 160);
                wmma::load_matrix_sync(fbl, g_W23l + ks * 16 * 160 + w * 16, 160);
#pragma unroll
                for (int m = 0; m < 4; m++) {
                    wmma::load_matrix_sync(fah, Hh + m * 16 * HLD + ks * 16, HLD);
                    wmma::load_matrix_sync(fal, Hl + m * 16 * HLD + ks * 16, HLD);
                    wmma::mma_sync(dacc[m], fah, fbh, dacc[m]);
                    wmma::mma_sync(dacc[m], fah, fbl, dacc[m]);
                    wmma::mma_sync(dacc[m], fal, fbh, dacc[m]);
                }
            }
            // theta += delta + b23   (warp w owns cols 16w..16w+15 -> no races)
#pragma unroll
            for (int m = 0; m < 4; m++) {
                wmma::store_matrix_sync(wscr, dacc[m], 16, wmma::mem_row_major);
                __syncwarp();
#pragma unroll
                for (int e = 0; e < 8; e++) {
                    int idx = lane * 8 + e;
                    int r = idx >> 4, c = idx & 15;
                    th[(m * 16 + r) * THS + w * 16 + c] +=
                        wscr[r * 16 + c] + g_b23[w * 16 + c];
                }
                __syncwarp();
            }
        }
        __syncthreads();
    }

    // ================= epilogue: rot6d -> rotmat, betas, camera ===============
    float* out_rot  = out;
    float* out_beta = out + (size_t)nrows * 216;
    float* out_cam  = out + (size_t)nrows * 226;

    for (int idx = tid; idx < MR * 24; idx += NT) {
        int r = idx / 24, g = idx - 24 * r;
        const float* tp = &th[r * THS + g * 6];
        float a1x = tp[0], a2x = tp[1];
        float a1y = tp[2], a2y = tp[3];
        float a1z = tp[4], a2z = tp[5];
        float n1 = sqrtf(a1x * a1x + a1y * a1y + a1z * a1z);
        float i1 = 1.f / fmaxf(n1, 1e-12f);
        float b1x = a1x * i1, b1y = a1y * i1, b1z = a1z * i1;
        float d = b1x * a2x + b1y * a2y + b1z * a2z;
        float c2x = a2x - d * b1x, c2y = a2y - d * b1y, c2z = a2z - d * b1z;
        float n2 = sqrtf(c2x * c2x + c2y * c2y + c2z * c2z);
        float i2 = 1.f / fmaxf(n2, 1e-12f);
        float b2x = c2x * i2, b2y = c2y * i2, b2z = c2z * i2;
        float b3x = b1y * b2z - b1z * b2y;
        float b3y = b1z * b2x - b1x * b2z;
        float b3z = b1x * b2y - b1y * b2x;
        float* o = out_rot + (size_t)(row0 + r) * 216 + g * 9;
        o[0] = b1x; o[1] = b2x; o[2] = b3x;
        o[3] = b1y; o[4] = b2y; o[5] = b3y;
        o[6] = b1z; o[7] = b2z; o[8] = b3z;
    }
    for (int idx = tid; idx < MR * 13; idx += NT) {
        int r = idx / 13, c = idx - 13 * r;
        if (c < 10)
            out_beta[(size_t)(row0 + r) * 10 + c] = th[r * THS + 144 + c];
        else
            out_cam[(size_t)(row0 + r) * 3 + (c - 10)] = th[r * THS + 154 + (c - 10)];
    }
}

// ---------------- launch ----------------
extern "C" void kernel_launch(void* const* d_in, const int* in_sizes, int n_in,
                              void* d_out, int out_size) {
    const float* x    = (const float*)d_in[0];
    const float* W1   = (const float*)d_in[2];
    const float* b1   = (const float*)d_in[3];
    const float* W2   = (const float*)d_in[4];
    const float* b2   = (const float*)d_in[5];
    const float* W3   = (const float*)d_in[6];
    const float* b3   = (const float*)d_in[7];
    const float* icr  = (const float*)d_in[8];
    const float* ish  = (const float*)d_in[9];
    const float* icam = (const float*)d_in[10];
    float* out = (float*)d_out;

    int nrows = in_sizes[0] / 256;  // 115200

    prep_theta0_k<<<1, 160>>>(icr, ish, icam);
    prep_W23p_k<<<256, 160>>>(W2, W3);
    prep_c1_k<<<1, 256>>>(W1, b1);
    prep_b23_k<<<1, 160>>>(b2, b3, W3);
    prep_splitW1_k<<<448, 256>>>(W1);
    prep_splitW23_k<<<256, 160>>>();

    cudaFuncSetAttribute(detr_wmma, cudaFuncAttributeMaxDynamicSharedMemorySize, SMEM_SZ);
    detr_wmma<<<nrows / MR, NT, SMEM_SZ>>>(x, b1, out, nrows);
}

// round 5
// speedup vs baseline: 1.6725x; 1.2159x over previous
#include <cuda_runtime.h>
#include <cuda_bf16.h>
#include <mma.h>
#include <cstdint>

using namespace nvcuda;

// ============================================================================
// DETRsmpl head: HMMA (wmma bf16 3-term hi/lo split, fp32 accum), sm_103 base.
// R5: B staged to SMEM via cp.async (double-buffered), A double-buffered,
//     prep kernels fused 6 -> 2.
// n=115200 rows, 64 rows/CTA, 1800 CTAs.
// ============================================================================

#define NT 512
#define MR 64
#define THS 161      // theta stride (f32)
#define ALD 40       // A stride (bf16)
#define BLD 264      // u-GEMM B smem stride (bf16)
#define BLD2 168     // delta B smem stride (bf16)
#define HLD 264      // H stride (bf16)

// smem byte offsets
#define OFF_TH   0        // f32 [64][161]              41216
#define OFF_A    41216    // 2 x (Ah 5120 + Al 5120)    20480
#define OFF_B    61696    // 2 x (Bh 16896 + Bl 16896)  67584
#define OFF_H    129280   // Hh 33792 + Hl 33792        67584
#define OFF_SCR  196864   // 16 warps x 256 f32         16384
#define OFF_SB   213248   // bias f32 [256]              1024
#define SMEM_SZ  214272

__device__ __nv_bfloat16 g_W1h[448 * 256];
__device__ __nv_bfloat16 g_W1l[448 * 256];
__device__ __nv_bfloat16 g_W23h[256 * 160];
__device__ __nv_bfloat16 g_W23l[256 * 160];
__device__ float g_W23p[256 * 160];
__device__ float g_c1[256];
__device__ float g_b23[160];
__device__ float g_theta0[160];

// ---------------- helpers ----------------
#define CP16(dst, src) asm volatile("cp.async.cg.shared.global [%0], [%1], 16;" :: "r"(dst), "l"(src))
#define CP_COMMIT()    asm volatile("cp.async.commit_group;" ::: "memory")
#define CP_WAIT0()     asm volatile("cp.async.wait_group 0;" ::: "memory")

__device__ __forceinline__ uint32_t pk2(__nv_bfloat16 a, __nv_bfloat16 b) {
    return (uint32_t)__bfloat16_as_ushort(a) | ((uint32_t)__bfloat16_as_ushort(b) << 16);
}

__device__ __forceinline__ void splitstore4(__nv_bfloat16* ph, __nv_bfloat16* pl, float4 v) {
    __nv_bfloat16 h0 = __float2bfloat16(v.x), h1 = __float2bfloat16(v.y);
    __nv_bfloat16 h2 = __float2bfloat16(v.z), h3 = __float2bfloat16(v.w);
    __nv_bfloat16 l0 = __float2bfloat16(v.x - __bfloat162float(h0));
    __nv_bfloat16 l1 = __float2bfloat16(v.y - __bfloat162float(h1));
    __nv_bfloat16 l2 = __float2bfloat16(v.z - __bfloat162float(h2));
    __nv_bfloat16 l3 = __float2bfloat16(v.w - __bfloat162float(h3));
    *reinterpret_cast<uint2*>(ph) = make_uint2(pk2(h0, h1), pk2(h2, h3));
    *reinterpret_cast<uint2*>(pl) = make_uint2(pk2(l0, l1), pk2(l2, l3));
}

// ---------------- fused prep kernels ----------------
// P1: blocks 0..447 -> split W1 ; block 0 also theta0 ; blocks 448..703 -> W23p
__global__ void prep1_k(const float* __restrict__ W1, const float* __restrict__ W2,
                        const float* __restrict__ W3, const float* __restrict__ icr,
                        const float* __restrict__ ish, const float* __restrict__ icam) {
    int b = blockIdx.x, t = threadIdx.x;
    if (b < 448) {
        float v = (b < 413) ? W1[b * 256 + t] : 0.f;
        __nv_bfloat16 h = __float2bfloat16(v);
        __nv_bfloat16 l = __float2bfloat16(v - __bfloat162float(h));
        g_W1h[b * 256 + t] = h;
        g_W1l[b * 256 + t] = l;
        if (b == 0 && t < 160) {
            float w = 0.f;
            if (t < 144) w = icr[t];
            else if (t < 154) w = ish[t - 144];
            else if (t < 157) w = icam[t - 154];
            g_theta0[t] = w;
        }
    } else {
        int k = b - 448;  // 0..255
        if (t < 160) {
            float s0 = 0, s1 = 0, s2 = 0, s3 = 0;
            if (t < 157) {
                for (int m = 0; m < 256; m += 4) {
                    s0 = fmaf(W2[k * 256 + m + 0], W3[(m + 0) * 157 + t], s0);
                    s1 = fmaf(W2[k * 256 + m + 1], W3[(m + 1) * 157 + t], s1);
                    s2 = fmaf(W2[k * 256 + m + 2], W3[(m + 2) * 157 + t], s2);
                    s3 = fmaf(W2[k * 256 + m + 3], W3[(m + 3) * 157 + t], s3);
                }
            }
            g_W23p[k * 160 + t] = (s0 + s1) + (s2 + s3);
        }
    }
}

// P2: block 0 -> c1 ; block 1 -> b23 ; blocks 2..257 -> split W23p
__global__ void prep2_k(const float* __restrict__ W1, const float* __restrict__ b1,
                        const float* __restrict__ b2, const float* __restrict__ b3,
                        const float* __restrict__ W3) {
    int b = blockIdx.x, t = threadIdx.x;
    if (b == 0) {
        float s = b1[t];
        for (int k = 0; k < 157; k++)
            s = fmaf(g_theta0[k], W1[(256 + k) * 256 + t], s);
        g_c1[t] = s;
    } else if (b == 1) {
        if (t < 160) {
            float s = 0.f;
            if (t < 157) {
                s = b3[t];
                for (int m = 0; m < 256; m++)
                    s = fmaf(b2[m], W3[m * 157 + t], s);
            }
            g_b23[t] = s;
        }
    } else {
        int k = b - 2;  // 0..255
        if (t < 160) {
            float v = g_W23p[k * 160 + t];
            __nv_bfloat16 h = __float2bfloat16(v);
            __nv_bfloat16 l = __float2bfloat16(v - __bfloat162float(h));
            g_W23h[k * 160 + t] = h;
            g_W23l[k * 160 + t] = l;
        }
    }
}

// ---------------- main kernel ----------------
typedef wmma::fragment<wmma::matrix_a, 16, 16, 16, __nv_bfloat16, wmma::row_major> FragA;
typedef wmma::fragment<wmma::matrix_b, 16, 16, 16, __nv_bfloat16, wmma::row_major> FragB;
typedef wmma::fragment<wmma::accumulator, 16, 16, 16, float> FragC;

__global__ __launch_bounds__(NT, 1)
void detr_wmma(const float* __restrict__ x, const float* __restrict__ b1g,
               float* __restrict__ out, int nrows) {
    extern __shared__ char smc[];
    float* th = reinterpret_cast<float*>(smc + OFF_TH);
    float* scr = reinterpret_cast<float*>(smc + OFF_SCR);
    float* sbias = reinterpret_cast<float*>(smc + OFF_SB);
    __nv_bfloat16* Hh = reinterpret_cast<__nv_bfloat16*>(smc + OFF_H);
    __nv_bfloat16* Hl = reinterpret_cast<__nv_bfloat16*>(smc + OFF_H + 33792);

    const int tid = threadIdx.x;
    const int w = tid >> 5, lane = tid & 31;
    const int row0 = blockIdx.x * MR;
    float* wscr = scr + w * 256;

    // ---- staging lambdas ----
    auto stageBu = [&](int kc, int buf) {   // W1 chunk: 32k x 256n, hi+lo
        uint32_t dbase = (uint32_t)__cvta_generic_to_shared(smc + OFF_B + buf * 33792);
#pragma unroll
        for (int i = 0; i < 4; i++) {
            int idx = tid + i * NT;                     // 0..2047
            int half = idx >> 10, e = idx & 1023;
            int row = e >> 5, col = e & 31;
            const __nv_bfloat16* src =
                (half ? g_W1l : g_W1h) + (size_t)(kc * 32 + row) * 256 + col * 8;
            uint32_t dst = dbase + half * 16896 + (row * BLD + col * 8) * 2;
            CP16(dst, src);
        }
    };
    auto stageBd = [&](int c, int buf) {    // W23 chunk: 32k x 160n, hi+lo
        uint32_t dbase = (uint32_t)__cvta_generic_to_shared(smc + OFF_B + buf * 33792);
#pragma unroll
        for (int i = 0; i < 3; i++) {
            int idx = tid + i * NT;                     // 0..1279 used
            if (idx < 1280) {
                int half = idx >= 640, e = idx - half * 640;
                int row = e / 20, col = e - row * 20;
                const __nv_bfloat16* src =
                    (half ? g_W23l : g_W23h) + (size_t)(c * 32 + row) * 160 + col * 8;
                uint32_t dst = dbase + half * 16896 + (row * BLD2 + col * 8) * 2;
                CP16(dst, src);
            }
        }
    };
    const int ar = tid >> 3, ac4 = tid & 7;  // A staging coords (64 x 8 float4)
    auto loadA = [&](int kc) -> float4 {
        if (kc < 8)
            return *reinterpret_cast<const float4*>(
                x + (size_t)(row0 + ar) * 256 + kc * 32 + ac4 * 4);
        const float* tr = &th[ar * THS + (kc - 8) * 32 + ac4 * 4];
        return make_float4(tr[0], tr[1], tr[2], tr[3]);
    };
    auto storeA = [&](float4 v, int buf) {
        __nv_bfloat16* Ah = reinterpret_cast<__nv_bfloat16*>(smc + OFF_A + buf * 10240);
        __nv_bfloat16* Al = Ah + 2560;
        splitstore4(&Ah[ar * ALD + ac4 * 4], &Al[ar * ALD + ac4 * 4], v);
    };

    // init theta tile = broadcast theta0
    for (int i = tid; i < MR * 160; i += NT) {
        int r = i / 160, c = i - 160 * r;
        th[r * THS + c] = g_theta0[c];
    }
    __syncthreads();

    for (int it = 0; it < 3; it++) {
        if (tid < 256) sbias[tid] = (it == 0) ? g_c1[tid] : b1g[tid];

        // ================= u-GEMM: [x|theta] @ W1, N=256 =====================
        FragC acc[4];
#pragma unroll
        for (int m = 0; m < 4; m++) wmma::fill_fragment(acc[m], 0.f);

        const int NC = (it == 0) ? 8 : 13;
        stageBu(0, 0); CP_COMMIT();
        storeA(loadA(0), 0);
        CP_WAIT0(); __syncthreads();

        for (int kc = 0; kc < NC; kc++) {
            const int cb = kc & 1, nb = cb ^ 1;
            float4 va;
            if (kc + 1 < NC) {
                stageBu(kc + 1, nb); CP_COMMIT();
                va = loadA(kc + 1);
            }
            {   // MMA on current buffers
                const __nv_bfloat16* Bh =
                    reinterpret_cast<const __nv_bfloat16*>(smc + OFF_B + cb * 33792);
                const __nv_bfloat16* Bl = Bh + 8448;
                const __nv_bfloat16* Ah =
                    reinterpret_cast<const __nv_bfloat16*>(smc + OFF_A + cb * 10240);
                const __nv_bfloat16* Al = Ah + 2560;
                FragA fah, fal;
                FragB fbh, fbl;
#pragma unroll
                for (int ks = 0; ks < 2; ks++) {
                    wmma::load_matrix_sync(fbh, Bh + ks * 16 * BLD + w * 16, BLD);
                    wmma::load_matrix_sync(fbl, Bl + ks * 16 * BLD + w * 16, BLD);
#pragma unroll
                    for (int m = 0; m < 4; m++) {
                        wmma::load_matrix_sync(fah, Ah + m * 16 * ALD + ks * 16, ALD);
                        wmma::load_matrix_sync(fal, Al + m * 16 * ALD + ks * 16, ALD);
                        wmma::mma_sync(acc[m], fah, fbh, acc[m]);
                        wmma::mma_sync(acc[m], fah, fbl, acc[m]);
                        wmma::mma_sync(acc[m], fal, fbh, acc[m]);
                    }
                }
            }
            if (kc + 1 < NC) storeA(va, nb);
            CP_WAIT0(); __syncthreads();
        }

        // prefetch first W23 chunk while converting H
        stageBd(0, 0); CP_COMMIT();

        // ========== bias + relu + split -> H panels ==========================
#pragma unroll
        for (int m = 0; m < 4; m++) {
            wmma::store_matrix_sync(wscr, acc[m], 16, wmma::mem_row_major);
            __syncwarp();
#pragma unroll
            for (int e = 0; e < 8; e++) {
                int idx = lane * 8 + e;
                int r = idx >> 4, c = idx & 15;
                float v = fmaxf(wscr[r * 16 + c] + sbias[w * 16 + c], 0.f);
                __nv_bfloat16 h = __float2bfloat16(v);
                __nv_bfloat16 l = __float2bfloat16(v - __bfloat162float(h));
                Hh[(m * 16 + r) * HLD + w * 16 + c] = h;
                Hl[(m * 16 + r) * HLD + w * 16 + c] = l;
            }
            __syncwarp();
        }
        CP_WAIT0(); __syncthreads();

        // ========== delta-GEMM: h @ W23, K=256, N=160 (10 warps) =============
        FragC dacc[4];
#pragma unroll
        for (int m = 0; m < 4; m++) wmma::fill_fragment(dacc[m], 0.f);

        for (int c = 0; c < 8; c++) {
            const int cb = c & 1, nb = cb ^ 1;
            if (c + 1 < 8) { stageBd(c + 1, nb); CP_COMMIT(); }
            if (w < 10) {
                const __nv_bfloat16* Bh =
                    reinterpret_cast<const __nv_bfloat16*>(smc + OFF_B + cb * 33792);
                const __nv_bfloat16* Bl = Bh + 8448;
                FragA fah, fal;
                FragB fbh, fbl;
#pragma unroll
                for (int ks = 0; ks < 2; ks++) {
                    const int kg = c * 32 + ks * 16;
                    wmma::load_matrix_sync(fbh, Bh + ks * 16 * BLD2 + w * 16, BLD2);
                    wmma::load_matrix_sync(fbl, Bl + ks * 16 * BLD2 + w * 16, BLD2);
#pragma unroll
                    for (int m = 0; m < 4; m++) {
                        wmma::load_matrix_sync(fah, Hh + m * 16 * HLD + kg, HLD);
                        wmma::load_matrix_sync(fal, Hl + m * 16 * HLD + kg, HLD);
                        wmma::mma_sync(dacc[m], fah, fbh, dacc[m]);
                        wmma::mma_sync(dacc[m], fah, fbl, dacc[m]);
                        wmma::mma_sync(dacc[m], fal, fbh, dacc[m]);
                    }
                }
            }
            CP_WAIT0(); __syncthreads();
        }

        // theta += delta + b23 (warp w owns cols 16w..16w+15)
        if (w < 10) {
#pragma unroll
            for (int m = 0; m < 4; m++) {
                wmma::store_matrix_sync(wscr, dacc[m], 16, wmma::mem_row_major);
                __syncwarp();
#pragma unroll
                for (int e = 0; e < 8; e++) {
                    int idx = lane * 8 + e;
                    int r = idx >> 4, c = idx & 15;
                    th[(m * 16 + r) * THS + w * 16 + c] +=
                        wscr[r * 16 + c] + g_b23[w * 16 + c];
                }
                __syncwarp();
            }
        }
        __syncthreads();
    }

    // ================= epilogue: rot6d -> rotmat, betas, camera ===============
    float* out_rot  = out;
    float* out_beta = out + (size_t)nrows * 216;
    float* out_cam  = out + (size_t)nrows * 226;

    for (int idx = tid; idx < MR * 24; idx += NT) {
        int r = idx / 24, g = idx - 24 * r;
        const float* tp = &th[r * THS + g * 6];
        float a1x = tp[0], a2x = tp[1];
        float a1y = tp[2], a2y = tp[3];
        float a1z = tp[4], a2z = tp[5];
        float n1 = sqrtf(a1x * a1x + a1y * a1y + a1z * a1z);
        float i1 = 1.f / fmaxf(n1, 1e-12f);
        float b1x = a1x * i1, b1y = a1y * i1, b1z = a1z * i1;
        float d = b1x * a2x + b1y * a2y + b1z * a2z;
        float c2x = a2x - d * b1x, c2y = a2y - d * b1y, c2z = a2z - d * b1z;
        float n2 = sqrtf(c2x * c2x + c2y * c2y + c2z * c2z);
        float i2 = 1.f / fmaxf(n2, 1e-12f);
        float b2x = c2x * i2, b2y = c2y * i2, b2z = c2z * i2;
        float b3x = b1y * b2z - b1z * b2y;
        float b3y = b1z * b2x - b1x * b2z;
        float b3z = b1x * b2y - b1y * b2x;
        float* o = out_rot + (size_t)(row0 + r) * 216 + g * 9;
        o[0] = b1x; o[1] = b2x; o[2] = b3x;
        o[3] = b1y; o[4] = b2y; o[5] = b3y;
        o[6] = b1z; o[7] = b2z; o[8] = b3z;
    }
    for (int idx = tid; idx < MR * 13; idx += NT) {
        int r = idx / 13, c = idx - 13 * r;
        if (c < 10)
            out_beta[(size_t)(row0 + r) * 10 + c] = th[r * THS + 144 + c];
        else
            out_cam[(size_t)(row0 + r) * 3 + (c - 10)] = th[r * THS + 154 + (c - 10)];
    }
}

// ---------------- launch ----------------
extern "C" void kernel_launch(void* const* d_in, const int* in_sizes, int n_in,
                              void* d_out, int out_size) {
    const float* x    = (const float*)d_in[0];
    const float* W1   = (const float*)d_in[2];
    const float* b1   = (const float*)d_in[3];
    const float* W2   = (const float*)d_in[4];
    const float* b2   = (const float*)d_in[5];
    const float* W3   = (const float*)d_in[6];
    const float* b3   = (const float*)d_in[7];
    const float* icr  = (const float*)d_in[8];
    const float* ish  = (const float*)d_in[9];
    const float* icam = (const float*)d_in[10];
    float* out = (float*)d_out;

    int nrows = in_sizes[0] / 256;  // 115200

    prep1_k<<<704, 256>>>(W1, W2, W3, icr, ish, icam);
    prep2_k<<<258, 256>>>(W1, b1, b2, b3, W3);

    cudaFuncSetAttribute(detr_wmma, cudaFuncAttributeMaxDynamicSharedMemorySize, SMEM_SZ);
    detr_wmma<<<nrows / MR, NT, SMEM_SZ>>>(x, b1, out, nrows);
}

// round 6
// speedup vs baseline: 2.0425x; 1.2212x over previous
#include <cuda_runtime.h>
#include <cuda_bf16.h>
#include <mma.h>
#include <cstdint>

using namespace nvcuda;

// ============================================================================
// DETRsmpl head: HMMA (wmma bf16 3-term hi/lo split, fp32 accum), sm_103 base.
// R6: xW1a hoisted into register fragments (computed once, reused 3 iters);
//     delta-GEMM padded to N=192 -> all 16 warps balanced (3 jobs each);
//     single fused prep kernel.
// n=115200 rows, 64 rows/CTA, 1800 CTAs.
// ============================================================================

#define NT 512
#define MR 64
#define THS 161      // theta stride (f32)
#define ALD 40       // A stride (bf16)
#define BLD 264      // u-GEMM B smem stride (bf16)
#define BLD2 200     // delta B smem stride (bf16)
#define HLD 264      // H stride (bf16)

// smem byte offsets
#define OFF_TH   0        // f32 [64][161]              41216
#define OFF_A    41216    // 2 x (Ah 5120 + Al 5120)    20480
#define OFF_B    61696    // 2 x (Bh 16896 + Bl 16896)  67584
#define OFF_H    129280   // Hh 33792 + Hl 33792        67584
#define OFF_SCR  196864   // 16 warps x 256 f32         16384
#define OFF_SB   213248   // bias f32 [256]              1024
#define SMEM_SZ  214272

__device__ __nv_bfloat16 g_W1h[448 * 256];
__device__ __nv_bfloat16 g_W1l[448 * 256];
__device__ __nv_bfloat16 g_W23h[256 * 192];   // padded N=192 (cols >=157 zero)
__device__ __nv_bfloat16 g_W23l[256 * 192];
__device__ float g_c1[256];
__device__ float g_b23[160];
__device__ float g_theta0[160];

// ---------------- helpers ----------------
#define CP16(dst, src) asm volatile("cp.async.cg.shared.global [%0], [%1], 16;" :: "r"(dst), "l"(src))
#define CP_COMMIT()    asm volatile("cp.async.commit_group;" ::: "memory")
#define CP_WAIT0()     asm volatile("cp.async.wait_group 0;" ::: "memory")

__device__ __forceinline__ uint32_t pk2(__nv_bfloat16 a, __nv_bfloat16 b) {
    return (uint32_t)__bfloat16_as_ushort(a) | ((uint32_t)__bfloat16_as_ushort(b) << 16);
}

__device__ __forceinline__ void splitstore4(__nv_bfloat16* ph, __nv_bfloat16* pl, float4 v) {
    __nv_bfloat16 h0 = __float2bfloat16(v.x), h1 = __float2bfloat16(v.y);
    __nv_bfloat16 h2 = __float2bfloat16(v.z), h3 = __float2bfloat16(v.w);
    __nv_bfloat16 l0 = __float2bfloat16(v.x - __bfloat162float(h0));
    __nv_bfloat16 l1 = __float2bfloat16(v.y - __bfloat162float(h1));
    __nv_bfloat16 l2 = __float2bfloat16(v.z - __bfloat162float(h2));
    __nv_bfloat16 l3 = __float2bfloat16(v.w - __bfloat162float(h3));
    *reinterpret_cast<uint2*>(ph) = make_uint2(pk2(h0, h1), pk2(h2, h3));
    *reinterpret_cast<uint2*>(pl) = make_uint2(pk2(l0, l1), pk2(l2, l3));
}

// ---------------- single fused prep kernel ----------------
// blocks 0..447   : split W1 row b (rows >=413 zero)
// blocks 448..703 : W23 row k = b-448: compute W2@W3 and split directly (N pad 192)
// block 704       : theta0
// block 705       : c1 (theta0 recomputed locally)
// block 706       : b23
__global__ void prep_k(const float* __restrict__ W1, const float* __restrict__ b1,
                       const float* __restrict__ W2, const float* __restrict__ b2,
                       const float* __restrict__ W3, const float* __restrict__ b3,
                       const float* __restrict__ icr, const float* __restrict__ ish,
                       const float* __restrict__ icam) {
    __shared__ float sth[160];
    int b = blockIdx.x, t = threadIdx.x;
    if (b < 448) {
        float v = (b < 413) ? W1[b * 256 + t] : 0.f;
        __nv_bfloat16 h = __float2bfloat16(v);
        __nv_bfloat16 l = __float2bfloat16(v - __bfloat162float(h));
        g_W1h[b * 256 + t] = h;
        g_W1l[b * 256 + t] = l;
    } else if (b < 704) {
        int k = b - 448;
        if (t < 192) {
            float s0 = 0, s1 = 0, s2 = 0, s3 = 0;
            if (t < 157) {
                for (int m = 0; m < 256; m += 4) {
                    s0 = fmaf(W2[k * 256 + m + 0], W3[(m + 0) * 157 + t], s0);
                    s1 = fmaf(W2[k * 256 + m + 1], W3[(m + 1) * 157 + t], s1);
                    s2 = fmaf(W2[k * 256 + m + 2], W3[(m + 2) * 157 + t], s2);
                    s3 = fmaf(W2[k * 256 + m + 3], W3[(m + 3) * 157 + t], s3);
                }
            }
            float v = (s0 + s1) + (s2 + s3);
            __nv_bfloat16 h = __float2bfloat16(v);
            __nv_bfloat16 l = __float2bfloat16(v - __bfloat162float(h));
            g_W23h[k * 192 + t] = h;
            g_W23l[k * 192 + t] = l;
        }
    } else if (b == 704) {
        if (t < 160) {
            float v = 0.f;
            if (t < 144) v = icr[t];
            else if (t < 154) v = ish[t - 144];
            else if (t < 157) v = icam[t - 154];
            g_theta0[t] = v;
        }
    } else if (b == 705) {
        if (t < 160) {
            float v = 0.f;
            if (t < 144) v = icr[t];
            else if (t < 154) v = ish[t - 144];
            else if (t < 157) v = icam[t - 154];
            sth[t] = v;
        }
        __syncthreads();
        float s = b1[t];
        for (int k = 0; k < 157; k++)
            s = fmaf(sth[k], W1[(256 + k) * 256 + t], s);
        g_c1[t] = s;
    } else {
        if (t < 160) {
            float s = 0.f;
            if (t < 157) {
                s = b3[t];
                for (int m = 0; m < 256; m++)
                    s = fmaf(b2[m], W3[m * 157 + t], s);
            }
            g_b23[t] = s;
        }
    }
}

// ---------------- main kernel ----------------
typedef wmma::fragment<wmma::matrix_a, 16, 16, 16, __nv_bfloat16, wmma::row_major> FragA;
typedef wmma::fragment<wmma::matrix_b, 16, 16, 16, __nv_bfloat16, wmma::row_major> FragB;
typedef wmma::fragment<wmma::accumulator, 16, 16, 16, float> FragC;

__global__ __launch_bounds__(NT, 1)
void detr_wmma(const float* __restrict__ x, const float* __restrict__ b1g,
               float* __restrict__ out, int nrows) {
    extern __shared__ char smc[];
    float* th = reinterpret_cast<float*>(smc + OFF_TH);
    float* scr = reinterpret_cast<float*>(smc + OFF_SCR);
    float* sbias = reinterpret_cast<float*>(smc + OFF_SB);
    __nv_bfloat16* Hh = reinterpret_cast<__nv_bfloat16*>(smc + OFF_H);
    __nv_bfloat16* Hl = reinterpret_cast<__nv_bfloat16*>(smc + OFF_H + 33792);

    const int tid = threadIdx.x;
    const int w = tid >> 5, lane = tid & 31;
    const int row0 = blockIdx.x * MR;
    float* wscr = scr + w * 256;

    // ---- staging lambdas ----
    auto stageBu = [&](int kc, int buf) {   // W1 chunk: 32k x 256n, hi+lo
        uint32_t dbase = (uint32_t)__cvta_generic_to_shared(smc + OFF_B + buf * 33792);
#pragma unroll
        for (int i = 0; i < 4; i++) {
            int idx = tid + i * NT;
            int half = idx >> 10, e = idx & 1023;
            int row = e >> 5, col = e & 31;
            const __nv_bfloat16* src =
                (half ? g_W1l : g_W1h) + (size_t)(kc * 32 + row) * 256 + col * 8;
            uint32_t dst = dbase + half * 16896 + (row * BLD + col * 8) * 2;
            CP16(dst, src);
        }
    };
    auto stageBd = [&](int c, int buf) {    // W23 chunk: 32k x 192n, hi+lo
        uint32_t dbase = (uint32_t)__cvta_generic_to_shared(smc + OFF_B + buf * 33792);
#pragma unroll
        for (int i = 0; i < 3; i++) {
            int idx = tid + i * NT;                     // 0..1535
            int half = idx >= 768, e = idx - half * 768;
            int row = e / 24, col = e - row * 24;
            const __nv_bfloat16* src =
                (half ? g_W23l : g_W23h) + (size_t)(c * 32 + row) * 192 + col * 8;
            uint32_t dst = dbase + half * 16896 + (row * BLD2 + col * 8) * 2;
            CP16(dst, src);
        }
    };
    const int ar = tid >> 3, ac4 = tid & 7;
    auto loadAx = [&](int kc) -> float4 {
        return *reinterpret_cast<const float4*>(
            x + (size_t)(row0 + ar) * 256 + kc * 32 + ac4 * 4);
    };
    auto loadAth = [&](int t) -> float4 {
        const float* tr = &th[ar * THS + t * 32 + ac4 * 4];
        return make_float4(tr[0], tr[1], tr[2], tr[3]);
    };
    auto storeA = [&](float4 v, int buf) {
        __nv_bfloat16* Ah = reinterpret_cast<__nv_bfloat16*>(smc + OFF_A + buf * 10240);
        __nv_bfloat16* Al = Ah + 2560;
        splitstore4(&Ah[ar * ALD + ac4 * 4], &Al[ar * ALD + ac4 * 4], v);
    };
    auto mmaChunk = [&](FragC* ac, int buf) {   // 3-term split MMA on current bufs
        const __nv_bfloat16* Bh =
            reinterpret_cast<const __nv_bfloat16*>(smc + OFF_B + buf * 33792);
        const __nv_bfloat16* Bl = Bh + 8448;
        const __nv_bfloat16* Ah =
            reinterpret_cast<const __nv_bfloat16*>(smc + OFF_A + buf * 10240);
        const __nv_bfloat16* Al = Ah + 2560;
        FragA fah, fal;
        FragB fbh, fbl;
#pragma unroll
        for (int ks = 0; ks < 2; ks++) {
            wmma::load_matrix_sync(fbh, Bh + ks * 16 * BLD + w * 16, BLD);
            wmma::load_matrix_sync(fbl, Bl + ks * 16 * BLD + w * 16, BLD);
#pragma unroll
            for (int m = 0; m < 4; m++) {
                wmma::load_matrix_sync(fah, Ah + m * 16 * ALD + ks * 16, ALD);
                wmma::load_matrix_sync(fal, Al + m * 16 * ALD + ks * 16, ALD);
                wmma::mma_sync(ac[m], fah, fbh, ac[m]);
                wmma::mma_sync(ac[m], fah, fbl, ac[m]);
                wmma::mma_sync(ac[m], fal, fbh, ac[m]);
            }
        }
    };

    // init theta tile = broadcast theta0
    for (int i = tid; i < MR * 160; i += NT) {
        int r = i / 160, c = i - 160 * r;
        th[r * THS + c] = g_theta0[c];
    }
    __syncthreads();

    // ================= xw = x @ W1a (once, kept in registers) ================
    FragC xw[4];
#pragma unroll
    for (int m = 0; m < 4; m++) wmma::fill_fragment(xw[m], 0.f);

    stageBu(0, 0); CP_COMMIT();
    storeA(loadAx(0), 0);
    CP_WAIT0(); __syncthreads();
    for (int kc = 0; kc < 8; kc++) {
        const int cb = kc & 1, nb = cb ^ 1;
        float4 va;
        if (kc < 7) { stageBu(kc + 1, nb); CP_COMMIT(); va = loadAx(kc + 1); }
        mmaChunk(xw, cb);
        if (kc < 7) storeA(va, nb);
        CP_WAIT0(); __syncthreads();
    }

    // ================= 3 refinement iterations ===============================
    for (int it = 0; it < 3; it++) {
        if (tid < 256) sbias[tid] = (it == 0) ? g_c1[tid] : b1g[tid];

        FragC acc[4];
#pragma unroll
        for (int m = 0; m < 4; m++)
#pragma unroll
            for (int e = 0; e < acc[m].num_elements; e++)
                acc[m].x[e] = xw[m].x[e];

        if (it > 0) {
            // theta @ W1b : 5 chunks (W1 rows 256..415 -> kc 8..12)
            stageBu(8, 0); CP_COMMIT();
            storeA(loadAth(0), 0);
            CP_WAIT0(); __syncthreads();
            for (int t = 0; t < 5; t++) {
                const int cb = t & 1, nb = cb ^ 1;
                float4 va;
                if (t < 4) { stageBu(9 + t, nb); CP_COMMIT(); va = loadAth(t + 1); }
                mmaChunk(acc, cb);
                if (t < 4) storeA(va, nb);
                CP_WAIT0(); __syncthreads();
            }
        } else {
            __syncthreads();  // sbias visible
        }

        // prefetch first W23 chunk while converting H
        stageBd(0, 0); CP_COMMIT();

        // ========== bias + relu + split -> H panels ==========================
#pragma unroll
        for (int m = 0; m < 4; m++) {
            wmma::store_matrix_sync(wscr, acc[m], 16, wmma::mem_row_major);
            __syncwarp();
#pragma unroll
            for (int e = 0; e < 8; e++) {
                int idx = lane * 8 + e;
                int r = idx >> 4, c = idx & 15;
                float v = fmaxf(wscr[r * 16 + c] + sbias[w * 16 + c], 0.f);
                __nv_bfloat16 h = __float2bfloat16(v);
                __nv_bfloat16 l = __float2bfloat16(v - __bfloat162float(h));
                Hh[(m * 16 + r) * HLD + w * 16 + c] = h;
                Hl[(m * 16 + r) * HLD + w * 16 + c] = l;
            }
            __syncwarp();
        }
        CP_WAIT0(); __syncthreads();

        // ========== delta-GEMM: h @ W23 (K=256, N=192pad, 16 warps x 3 jobs) =
        // warp w: m = w&3 fixed, n = (w>>2) + 4j for j=0..2
        const int dm = w & 3, dn0 = w >> 2;
        FragC dacc[3];
#pragma unroll
        for (int j = 0; j < 3; j++) wmma::fill_fragment(dacc[j], 0.f);

        for (int c = 0; c < 8; c++) {
            const int cb = c & 1, nb = cb ^ 1;
            if (c + 1 < 8) { stageBd(c + 1, nb); CP_COMMIT(); }
            {
                const __nv_bfloat16* Bh =
                    reinterpret_cast<const __nv_bfloat16*>(smc + OFF_B + cb * 33792);
                const __nv_bfloat16* Bl = Bh + 8448;
                FragA fah, fal;
                FragB fbh, fbl;
#pragma unroll
                for (int ks = 0; ks < 2; ks++) {
                    const int kg = c * 32 + ks * 16;
                    wmma::load_matrix_sync(fah, Hh + dm * 16 * HLD + kg, HLD);
                    wmma::load_matrix_sync(fal, Hl + dm * 16 * HLD + kg, HLD);
#pragma unroll
                    for (int j = 0; j < 3; j++) {
                        const int n = dn0 + 4 * j;
                        wmma::load_matrix_sync(fbh, Bh + ks * 16 * BLD2 + n * 16, BLD2);
                        wmma::load_matrix_sync(fbl, Bl + ks * 16 * BLD2 + n * 16, BLD2);
                        wmma::mma_sync(dacc[j], fah, fbh, dacc[j]);
                        wmma::mma_sync(dacc[j], fah, fbl, dacc[j]);
                        wmma::mma_sync(dacc[j], fal, fbh, dacc[j]);
                    }
                }
            }
            CP_WAIT0(); __syncthreads();
        }

        // theta += delta + b23  (job (dm, n) unique -> no races; skip n>=10)
#pragma unroll
        for (int j = 0; j < 3; j++) {
            const int n = dn0 + 4 * j;
            if (n < 10) {
                wmma::store_matrix_sync(wscr, dacc[j], 16, wmma::mem_row_major);
                __syncwarp();
#pragma unroll
                for (int e = 0; e < 8; e++) {
                    int idx = lane * 8 + e;
                    int r = idx >> 4, c = idx & 15;
                    th[(dm * 16 + r) * THS + n * 16 + c] +=
                        wscr[r * 16 + c] + g_b23[n * 16 + c];
                }
                __syncwarp();
            }
        }
        __syncthreads();
    }

    // ================= epilogue: rot6d -> rotmat, betas, camera ===============
    float* out_rot  = out;
    float* out_beta = out + (size_t)nrows * 216;
    float* out_cam  = out + (size_t)nrows * 226;

    for (int idx = tid; idx < MR * 24; idx += NT) {
        int r = idx / 24, g = idx - 24 * r;
        const float* tp = &th[r * THS + g * 6];
        float a1x = tp[0], a2x = tp[1];
        float a1y = tp[2], a2y = tp[3];
        float a1z = tp[4], a2z = tp[5];
        float n1 = sqrtf(a1x * a1x + a1y * a1y + a1z * a1z);
        float i1 = 1.f / fmaxf(n1, 1e-12f);
        float b1x = a1x * i1, b1y = a1y * i1, b1z = a1z * i1;
        float d = b1x * a2x + b1y * a2y + b1z * a2z;
        float c2x = a2x - d * b1x, c2y = a2y - d * b1y, c2z = a2z - d * b1z;
        float n2 = sqrtf(c2x * c2x + c2y * c2y + c2z * c2z);
        float i2 = 1.f / fmaxf(n2, 1e-12f);
        float b2x = c2x * i2, b2y = c2y * i2, b2z = c2z * i2;
        float b3x = b1y * b2z - b1z * b2y;
        float b3y = b1z * b2x - b1x * b2z;
        float b3z = b1x * b2y - b1y * b2x;
        float* o = out_rot + (size_t)(row0 + r) * 216 + g * 9;
        o[0] = b1x; o[1] = b2x; o[2] = b3x;
        o[3] = b1y; o[4] = b2y; o[5] = b3y;
        o[6] = b1z; o[7] = b2z; o[8] = b3z;
    }
    for (int idx = tid; idx < MR * 13; idx += NT) {
        int r = idx / 13, c = idx - 13 * r;
        if (c < 10)
            out_beta[(size_t)(row0 + r) * 10 + c] = th[r * THS + 144 + c];
        else
            out_cam[(size_t)(row0 + r) * 3 + (c - 10)] = th[r * THS + 154 + (c - 10)];
    }
}

// ---------------- launch ----------------
extern "C" void kernel_launch(void* const* d_in, const int* in_sizes, int n_in,
                              void* d_out, int out_size) {
    const float* x    = (const float*)d_in[0];
    const float* W1   = (const float*)d_in[2];
    const float* b1   = (const float*)d_in[3];
    const float* W2   = (const float*)d_in[4];
    const float* b2   = (const float*)d_in[5];
    const float* W3   = (const float*)d_in[6];
    const float* b3   = (const float*)d_in[7];
    const float* icr  = (const float*)d_in[8];
    const float* ish  = (const float*)d_in[9];
    const float* icam = (const float*)d_in[10];
    float* out = (float*)d_out;

    int nrows = in_sizes[0] / 256;  // 115200

    prep_k<<<707, 256>>>(W1, b1, W2, b2, W3, b3, icr, ish, icam);

    cudaFuncSetAttribute(detr_wmma, cudaFuncAttributeMaxDynamicSharedMemorySize, SMEM_SZ);
    detr_wmma<<<nrows / MR, NT, SMEM_SZ>>>(x, b1, out, nrows);
}

// round 7
// speedup vs baseline: 2.5254x; 1.2364x over previous
#include <cuda_runtime.h>
#include <cuda_bf16.h>
#include <mma.h>
#include <cstdint>

using namespace nvcuda;

// ============================================================================
// DETRsmpl head, HMMA bf16 3-term split, sm_103 base. R7: recurrence collapse.
//   u0 = x@W1a + c1 ; h_i = relu(u_i-bias) ; u_{i+1} = u_i + h_i@W231
//   theta = (theta0 + 3 b23) + (h0+h1+h2)@W23     [W231 = W23@W1b precomputed]
// 64 rows/CTA, 1800 CTAs, 512 threads. acc persistent in registers.
// ============================================================================

#define NT 512
#define MR 64
#define HLD 264      // H/A panel stride (bf16)
#define HS_LD 260    // Hsum f32 stride
#define BLD 264      // 256-wide B chunk stride (bf16)
#define BLD2 200     // 192-wide B chunk stride (bf16)

// smem layout (bytes)
#define OFF_H    0        // Hh 33792 | Hl 33792
#define OFF_HS   67584    // Hsum f32 64x260 = 66560 (reused as theta at end)
#define OFF_B    134144   // 2 x 33792
#define OFF_SCR  201728   // 16 x 256 f32
#define OFF_SB   218112   // bias 256 f32
#define SMEM_SZ  219136

__device__ __nv_bfloat16 g_W1h[256 * 256];    // W1a split
__device__ __nv_bfloat16 g_W1l[256 * 256];
__device__ __nv_bfloat16 g_W231h[256 * 256];  // (W2@W3@W1b) split
__device__ __nv_bfloat16 g_W231l[256 * 256];
__device__ __nv_bfloat16 g_W23h[256 * 192];   // (W2@W3) split, N pad 192
__device__ __nv_bfloat16 g_W23l[256 * 192];
__device__ float g_W23p[256 * 192];
__device__ float g_c1[256];
__device__ float g_cb[3 * 256];               // bias_i = c1 + i*cvec
__device__ float g_b23[160];
__device__ float g_theta0[160];
__device__ float g_tfin[160];                 // theta0 + 3*b23

// ---------------- helpers ----------------
#define CP16(dst, src) asm volatile("cp.async.cg.shared.global [%0], [%1], 16;" :: "r"(dst), "l"(src))
#define CP_COMMIT()    asm volatile("cp.async.commit_group;" ::: "memory")
#define CP_WAIT0()     asm volatile("cp.async.wait_group 0;" ::: "memory")

__device__ __forceinline__ uint32_t pk2(__nv_bfloat16 a, __nv_bfloat16 b) {
    return (uint32_t)__bfloat16_as_ushort(a) | ((uint32_t)__bfloat16_as_ushort(b) << 16);
}

__device__ __forceinline__ void splitstore4(__nv_bfloat16* ph, __nv_bfloat16* pl, float4 v) {
    __nv_bfloat16 h0 = __float2bfloat16(v.x), h1 = __float2bfloat16(v.y);
    __nv_bfloat16 h2 = __float2bfloat16(v.z), h3 = __float2bfloat16(v.w);
    __nv_bfloat16 l0 = __float2bfloat16(v.x - __bfloat162float(h0));
    __nv_bfloat16 l1 = __float2bfloat16(v.y - __bfloat162float(h1));
    __nv_bfloat16 l2 = __float2bfloat16(v.z - __bfloat162float(h2));
    __nv_bfloat16 l3 = __float2bfloat16(v.w - __bfloat162float(h3));
    *reinterpret_cast<uint2*>(ph) = make_uint2(pk2(h0, h1), pk2(h2, h3));
    *reinterpret_cast<uint2*>(pl) = make_uint2(pk2(l0, l1), pk2(l2, l3));
}

// ---------------- prep kernels ----------------
// P1: b<256 split W1a row; 256..511 W23p row + split; 512 theta0; 513 c1; 514 b23+tfin
__global__ void prep1_k(const float* __restrict__ W1, const float* __restrict__ b1,
                        const float* __restrict__ W2, const float* __restrict__ b2,
                        const float* __restrict__ W3, const float* __restrict__ b3,
                        const float* __restrict__ icr, const float* __restrict__ ish,
                        const float* __restrict__ icam) {
    __shared__ float sth[160];
    int b = blockIdx.x, t = threadIdx.x;
    if (b < 256) {
        float v = W1[b * 256 + t];
        __nv_bfloat16 h = __float2bfloat16(v);
        __nv_bfloat16 l = __float2bfloat16(v - __bfloat162float(h));
        g_W1h[b * 256 + t] = h;
        g_W1l[b * 256 + t] = l;
    } else if (b < 512) {
        int k = b - 256;
        if (t < 192) {
            float s0 = 0, s1 = 0, s2 = 0, s3 = 0;
            if (t < 157) {
                for (int m = 0; m < 256; m += 4) {
                    s0 = fmaf(W2[k * 256 + m + 0], W3[(m + 0) * 157 + t], s0);
                    s1 = fmaf(W2[k * 256 + m + 1], W3[(m + 1) * 157 + t], s1);
                    s2 = fmaf(W2[k * 256 + m + 2], W3[(m + 2) * 157 + t], s2);
                    s3 = fmaf(W2[k * 256 + m + 3], W3[(m + 3) * 157 + t], s3);
                }
            }
            float v = (s0 + s1) + (s2 + s3);
            g_W23p[k * 192 + t] = v;
            __nv_bfloat16 h = __float2bfloat16(v);
            __nv_bfloat16 l = __float2bfloat16(v - __bfloat162float(h));
            g_W23h[k * 192 + t] = h;
            g_W23l[k * 192 + t] = l;
        }
    } else if (b == 512) {
        if (t < 160) {
            float v = 0.f;
            if (t < 144) v = icr[t];
            else if (t < 154) v = ish[t - 144];
            else if (t < 157) v = icam[t - 154];
            g_theta0[t] = v;
        }
    } else if (b == 513) {
        if (t < 160) {
            float v = 0.f;
            if (t < 144) v = icr[t];
            else if (t < 154) v = ish[t - 144];
            else if (t < 157) v = icam[t - 154];
            sth[t] = v;
        }
        __syncthreads();
        float s = b1[t];
        for (int k = 0; k < 157; k++)
            s = fmaf(sth[k], W1[(256 + k) * 256 + t], s);
        g_c1[t] = s;
    } else {
        if (t < 160) {
            float s = 0.f;
            if (t < 157) {
                s = b3[t];
                for (int m = 0; m < 256; m++)
                    s = fmaf(b2[m], W3[m * 157 + t], s);
            }
            g_b23[t] = s;
            float v = 0.f;
            if (t < 144) v = icr[t];
            else if (t < 154) v = ish[t - 144];
            else if (t < 157) v = icam[t - 154];
            g_tfin[t] = v + 3.f * s;
        }
    }
}

// P2 (needs P1): b<256 -> W231 row split ; b==256 -> cvec/cb vectors
__global__ void prep2_k(const float* __restrict__ W1) {
    int b = blockIdx.x, t = threadIdx.x;
    if (b < 256) {
        float s = 0.f;
        for (int k = 0; k < 157; k++)
            s = fmaf(g_W23p[b * 192 + k], W1[(256 + k) * 256 + t], s);
        __nv_bfloat16 h = __float2bfloat16(s);
        __nv_bfloat16 l = __float2bfloat16(s - __bfloat162float(h));
        g_W231h[b * 256 + t] = h;
        g_W231l[b * 256 + t] = l;
    } else {
        float cv = 0.f;
        for (int k = 0; k < 157; k++)
            cv = fmaf(g_b23[k], W1[(256 + k) * 256 + t], cv);
        float c1 = g_c1[t];
        g_cb[0 * 256 + t] = c1;
        g_cb[1 * 256 + t] = c1 + cv;
        g_cb[2 * 256 + t] = c1 + 2.f * cv;
    }
}

// ---------------- main kernel ----------------
typedef wmma::fragment<wmma::matrix_a, 16, 16, 16, __nv_bfloat16, wmma::row_major> FragA;
typedef wmma::fragment<wmma::matrix_b, 16, 16, 16, __nv_bfloat16, wmma::row_major> FragB;
typedef wmma::fragment<wmma::accumulator, 16, 16, 16, float> FragC;

__global__ __launch_bounds__(NT, 1)
void detr_wmma(const float* __restrict__ x, float* __restrict__ out, int nrows) {
    extern __shared__ char smc[];
    __nv_bfloat16* Hh = reinterpret_cast<__nv_bfloat16*>(smc + OFF_H);
    __nv_bfloat16* Hl = reinterpret_cast<__nv_bfloat16*>(smc + OFF_H + 33792);
    float* Hs = reinterpret_cast<float*>(smc + OFF_HS);
    float* scr = reinterpret_cast<float*>(smc + OFF_SCR);
    float* sbias = reinterpret_cast<float*>(smc + OFF_SB);

    const int tid = threadIdx.x;
    const int w = tid >> 5, lane = tid & 31;
    const int mg = w >> 3, ng = w & 7;       // u-GEMM: 2m x 2n warp tile
    const int row0 = blockIdx.x * MR;
    float* wscr = scr + w * 256;

    // 256-wide B chunk stage (hi|lo), 32 k-rows
    auto stageB256 = [&](const __nv_bfloat16* hi, const __nv_bfloat16* lo,
                         int kc, int buf) {
        uint32_t dbase = (uint32_t)__cvta_generic_to_shared(smc + OFF_B + buf * 33792);
#pragma unroll
        for (int i = 0; i < 4; i++) {
            int idx = tid + i * NT;
            int half = idx >> 10, e = idx & 1023;
            int row = e >> 5, col = e & 31;
            const __nv_bfloat16* src = (half ? lo : hi) + (size_t)(kc * 32 + row) * 256 + col * 8;
            uint32_t dst = dbase + half * 16896 + (row * BLD + col * 8) * 2;
            CP16(dst, src);
        }
    };
    // 192-wide B chunk stage
    auto stageB192 = [&](int kc, int buf) {
        uint32_t dbase = (uint32_t)__cvta_generic_to_shared(smc + OFF_B + buf * 33792);
#pragma unroll
        for (int i = 0; i < 3; i++) {
            int idx = tid + i * NT;
            int half = idx >= 768, e = idx - half * 768;
            int row = e / 24, col = e - row * 24;
            const __nv_bfloat16* src =
                (half ? g_W23l : g_W23h) + (size_t)(kc * 32 + row) * 192 + col * 8;
            uint32_t dst = dbase + half * 16896 + (row * BLD2 + col * 8) * 2;
            CP16(dst, src);
        }
    };
    // u-GEMM chunk: A = panels (full K), B = staged chunk; 2m x 2n, 3-term
    auto mmaChunk2 = [&](FragC* acc, int kc, int buf) {
        const __nv_bfloat16* Bh = reinterpret_cast<const __nv_bfloat16*>(smc + OFF_B + buf * 33792);
        const __nv_bfloat16* Bl = reinterpret_cast<const __nv_bfloat16*>(smc + OFF_B + buf * 33792 + 16896);
        FragA fah, fal;
        FragB fb0h, fb0l, fb1h, fb1l;
#pragma unroll
        for (int ks = 0; ks < 2; ks++) {
            const int kg = kc * 32 + ks * 16;
            wmma::load_matrix_sync(fb0h, Bh + ks * 16 * BLD + (ng * 2 + 0) * 16, BLD);
            wmma::load_matrix_sync(fb0l, Bl + ks * 16 * BLD + (ng * 2 + 0) * 16, BLD);
            wmma::load_matrix_sync(fb1h, Bh + ks * 16 * BLD + (ng * 2 + 1) * 16, BLD);
            wmma::load_matrix_sync(fb1l, Bl + ks * 16 * BLD + (ng * 2 + 1) * 16, BLD);
#pragma unroll
            for (int mi = 0; mi < 2; mi++) {
                wmma::load_matrix_sync(fah, Hh + (mg * 2 + mi) * 16 * HLD + kg, HLD);
                wmma::load_matrix_sync(fal, Hl + (mg * 2 + mi) * 16 * HLD + kg, HLD);
                wmma::mma_sync(acc[mi * 2 + 0], fah, fb0h, acc[mi * 2 + 0]);
                wmma::mma_sync(acc[mi * 2 + 0], fah, fb0l, acc[mi * 2 + 0]);
                wmma::mma_sync(acc[mi * 2 + 0], fal, fb0h, acc[mi * 2 + 0]);
                wmma::mma_sync(acc[mi * 2 + 1], fah, fb1h, acc[mi * 2 + 1]);
                wmma::mma_sync(acc[mi * 2 + 1], fah, fb1l, acc[mi * 2 + 1]);
                wmma::mma_sync(acc[mi * 2 + 1], fal, fb1h, acc[mi * 2 + 1]);
            }
        }
    };

    // ---- stage x split into panels (once) + prefetch W1a chunk 0 ----
    stageB256(g_W1h, g_W1l, 0, 0); CP_COMMIT();
    {
        const int r = tid >> 3, c0 = tid & 7;
        const float* xr = x + (size_t)(row0 + r) * 256;
#pragma unroll
        for (int q = 0; q < 8; q++) {
            const int c4 = c0 + 8 * q;
            float4 v = *reinterpret_cast<const float4*>(xr + c4 * 4);
            splitstore4(&Hh[r * HLD + c4 * 4], &Hl[r * HLD + c4 * 4], v);
        }
    }
    CP_WAIT0(); __syncthreads();

    // ---- phase A: acc = x @ W1a ----
    FragC acc[4];
#pragma unroll
    for (int i = 0; i < 4; i++) wmma::fill_fragment(acc[i], 0.f);
    for (int kc = 0; kc < 8; kc++) {
        const int cb = kc & 1;
        if (kc < 7) { stageB256(g_W1h, g_W1l, kc + 1, cb ^ 1); CP_COMMIT(); }
        mmaChunk2(acc, kc, cb);
        CP_WAIT0(); __syncthreads();
    }

    // ---- 3 iterations: convert + (it<2) acc += h @ W231 ----
    for (int it = 0; it < 3; it++) {
        if (tid < 256) sbias[tid] = g_cb[it * 256 + tid];
        if (it < 2) stageB256(g_W231h, g_W231l, 0, 0); else stageB192(0, 0);
        CP_COMMIT();
        __syncthreads();

        // h = relu(acc + bias); panels <- (it<2 ? h : Hsum + h); Hsum accumulate
#pragma unroll
        for (int mi = 0; mi < 2; mi++) {
#pragma unroll
            for (int nj = 0; nj < 2; nj++) {
                wmma::store_matrix_sync(wscr, acc[mi * 2 + nj], 16, wmma::mem_row_major);
                __syncwarp();
                const int gr = (mg * 2 + mi) * 16, gc = (ng * 2 + nj) * 16;
#pragma unroll
                for (int e = 0; e < 8; e++) {
                    int idx = lane * 8 + e;
                    int r = idx >> 4, c = idx & 15;
                    int row = gr + r, col = gc + c;
                    float h = fmaxf(wscr[r * 16 + c] + sbias[col], 0.f);
                    if (it == 0) Hs[row * HS_LD + col] = h;
                    else if (it == 1) Hs[row * HS_LD + col] += h;
                    else h += Hs[row * HS_LD + col];
                    __nv_bfloat16 hh = __float2bfloat16(h);
                    __nv_bfloat16 hl = __float2bfloat16(h - __bfloat162float(hh));
                    Hh[row * HLD + col] = hh;
                    Hl[row * HLD + col] = hl;
                }
                __syncwarp();
            }
        }
        CP_WAIT0(); __syncthreads();

        if (it < 2) {
            for (int kc = 0; kc < 8; kc++) {
                const int cb = kc & 1;
                if (kc < 7) { stageB256(g_W231h, g_W231l, kc + 1, cb ^ 1); CP_COMMIT(); }
                mmaChunk2(acc, kc, cb);
                CP_WAIT0(); __syncthreads();
            }
        }
    }

    // ---- final delta: dacc = Hsum_panels @ W23 (N=192, warp: 1m x 3n) ----
    const int dm = w & 3, ng3 = w >> 2;
    FragC dacc[3];
#pragma unroll
    for (int j = 0; j < 3; j++) wmma::fill_fragment(dacc[j], 0.f);

    for (int kc = 0; kc < 8; kc++) {
        const int cb = kc & 1;
        if (kc < 7) { stageB192(kc + 1, cb ^ 1); CP_COMMIT(); }
        {
            const __nv_bfloat16* Bh = reinterpret_cast<const __nv_bfloat16*>(smc + OFF_B + cb * 33792);
            const __nv_bfloat16* Bl = reinterpret_cast<const __nv_bfloat16*>(smc + OFF_B + cb * 33792 + 16896);
            FragA fah, fal;
            FragB fbh, fbl;
#pragma unroll
            for (int ks = 0; ks < 2; ks++) {
                const int kg = kc * 32 + ks * 16;
                wmma::load_matrix_sync(fah, Hh + dm * 16 * HLD + kg, HLD);
                wmma::load_matrix_sync(fal, Hl + dm * 16 * HLD + kg, HLD);
#pragma unroll
                for (int j = 0; j < 3; j++) {
                    const int n = ng3 + 4 * j;
                    wmma::load_matrix_sync(fbh, Bh + ks * 16 * BLD2 + n * 16, BLD2);
                    wmma::load_matrix_sync(fbl, Bl + ks * 16 * BLD2 + n * 16, BLD2);
                    wmma::mma_sync(dacc[j], fah, fbh, dacc[j]);
                    wmma::mma_sync(dacc[j], fah, fbl, dacc[j]);
                    wmma::mma_sync(dacc[j], fal, fbh, dacc[j]);
                }
            }
        }
        CP_WAIT0(); __syncthreads();
    }

    // ---- theta = tfin + dacc  (into Hsum buffer, stride HS_LD) ----
    float* th = Hs;
#pragma unroll
    for (int j = 0; j < 3; j++) {
        const int n = ng3 + 4 * j;
        if (n < 10) {
            wmma::store_matrix_sync(wscr, dacc[j], 16, wmma::mem_row_major);
            __syncwarp();
#pragma unroll
            for (int e = 0; e < 8; e++) {
                int idx = lane * 8 + e;
                int r = idx >> 4, c = idx & 15;
                th[(dm * 16 + r) * HS_LD + n * 16 + c] =
                    wscr[r * 16 + c] + g_tfin[n * 16 + c];
            }
            __syncwarp();
        }
    }
    __syncthreads();

    // ---- epilogue: rot6d -> rotmat, betas, camera ----
    float* out_rot  = out;
    float* out_beta = out + (size_t)nrows * 216;
    float* out_cam  = out + (size_t)nrows * 226;

    for (int idx = tid; idx < MR * 24; idx += NT) {
        int r = idx / 24, g = idx - 24 * r;
        const float* tp = &th[r * HS_LD + g * 6];
        float a1x = tp[0], a2x = tp[1];
        float a1y = tp[2], a2y = tp[3];
        float a1z = tp[4], a2z = tp[5];
        float n1 = sqrtf(a1x * a1x + a1y * a1y + a1z * a1z);
        float i1 = 1.f / fmaxf(n1, 1e-12f);
        float b1x = a1x * i1, b1y = a1y * i1, b1z = a1z * i1;
        float d = b1x * a2x + b1y * a2y + b1z * a2z;
        float c2x = a2x - d * b1x, c2y = a2y - d * b1y, c2z = a2z - d * b1z;
        float n2 = sqrtf(c2x * c2x + c2y * c2y + c2z * c2z);
        float i2 = 1.f / fmaxf(n2, 1e-12f);
        float b2x = c2x * i2, b2y = c2y * i2, b2z = c2z * i2;
        float b3x = b1y * b2z - b1z * b2y;
        float b3y = b1z * b2x - b1x * b2z;
        float b3z = b1x * b2y - b1y * b2x;
        float* o = out_rot + (size_t)(row0 + r) * 216 + g * 9;
        o[0] = b1x; o[1] = b2x; o[2] = b3x;
        o[3] = b1y; o[4] = b2y; o[5] = b3y;
        o[6] = b1z; o[7] = b2z; o[8] = b3z;
    }
    for (int idx = tid; idx < MR * 13; idx += NT) {
        int r = idx / 13, c = idx - 13 * r;
        if (c < 10)
            out_beta[(size_t)(row0 + r) * 10 + c] = th[r * HS_LD + 144 + c];
        else
            out_cam[(size_t)(row0 + r) * 3 + (c - 10)] = th[r * HS_LD + 154 + (c - 10)];
    }
}

// ---------------- launch ----------------
extern "C" void kernel_launch(void* const* d_in, const int* in_sizes, int n_in,
                              void* d_out, int out_size) {
    const float* x    = (const float*)d_in[0];
    const float* W1   = (const float*)d_in[2];
    const float* b1   = (const float*)d_in[3];
    const float* W2   = (const float*)d_in[4];
    const float* b2   = (const float*)d_in[5];
    const float* W3   = (const float*)d_in[6];
    const float* b3   = (const float*)d_in[7];
    const float* icr  = (const float*)d_in[8];
    const float* ish  = (const float*)d_in[9];
    const float* icam = (const float*)d_in[10];
    float* out = (float*)d_out;

    int nrows = in_sizes[0] / 256;  // 115200

    prep1_k<<<515, 256>>>(W1, b1, W2, b2, W3, b3, icr, ish, icam);
    prep2_k<<<257, 256>>>(W1);

    cudaFuncSetAttribute(detr_wmma, cudaFuncAttributeMaxDynamicSharedMemorySize, SMEM_SZ);
    detr_wmma<<<nrows / MR, NT, SMEM_SZ>>>(x, out, nrows);
}